// round 16
// baseline (speedup 1.0000x reference)
#include <cuda_runtime.h>
#include <math.h>

#define HB   64
#define HDIM 131072
#define HN1  512
#define HN2  256
#define CSS  656             // column stride (float2) for in-place 512-FFT: S[648] + pad
#define MAP(i) ((i) + ((i) >> 3))   // padded intermediate layout (conflict reduction)
#define MWS  800             // k_mid per-warp smem: X0[256] X1[256] Y[288]

#define BARCOL(id) asm volatile("bar.sync %0, %1;" :: "r"(id), "r"(64) : "memory")

// Static device scratch (allowed; no runtime allocation)
static __device__ float2 g_bufA[(size_t)HB * HDIM];        // 64 MB  fwd stage-1 out
static __device__ float2 g_bufP[(size_t)(HB / 2) * HDIM];  // 32 MB  packed G per row pair
static __device__ unsigned g_maxbits;                      // zero-init; atomicMax idempotent
static __device__ float2 g_gates[HB];                      // (store, retrieve) per row

__device__ __forceinline__ float2 cmulf(float2 a, float2 b) {
    return make_float2(fmaf(a.x, b.x, -a.y * b.y), fmaf(a.x, b.y, a.y * b.x));
}
__device__ __forceinline__ float2 cadd(float2 a, float2 b) { return make_float2(a.x + b.x, a.y + b.y); }
__device__ __forceinline__ float2 csub(float2 a, float2 b) { return make_float2(a.x - b.x, a.y - b.y); }
template<bool INV> __device__ __forceinline__ float2 mulmi(float2 v) {   // *(−i) fwd, *(+i) inv
    return INV ? make_float2(-v.y, v.x) : make_float2(v.y, -v.x);
}
__device__ __forceinline__ float2 shfl_c(float2 v, int src) {
    return make_float2(__shfl_sync(0xffffffffu, v.x, src), __shfl_sync(0xffffffffu, v.y, src));
}
// e^{-2*pi*i * a / HDIM} in registers; a < 2^24 so (float)a exact, /65536 exact.
__device__ __forceinline__ float2 twu(int a) {
    float s, c;
    sincospif((float)a * (1.0f / 65536.0f), &s, &c);
    return make_float2(c, -s);
}

// 8-point DFT in registers, natural in/out order.
template<bool INV> __device__ __forceinline__ void dft8(float2* c) {
    const float s = 0.70710678118654752440f;
    float2 e0 = c[0], e1 = c[4], e2 = c[2], e3 = c[6], e4 = c[1], e5 = c[5], e6 = c[3], e7 = c[7];
    float2 f0 = cadd(e0, e1), f1 = csub(e0, e1), f2 = cadd(e2, e3), f3 = csub(e2, e3);
    float2 f4 = cadd(e4, e5), f5 = csub(e4, e5), f6 = cadd(e6, e7), f7 = csub(e6, e7);
    float2 t3 = mulmi<INV>(f3), t7 = mulmi<INV>(f7);
    float2 g0 = cadd(f0, f2), g2 = csub(f0, f2), g1 = cadd(f1, t3), g3 = csub(f1, t3);
    float2 g4 = cadd(f4, f6), g6 = csub(f4, f6), g5 = cadd(f5, t7), g7 = csub(f5, t7);
    float2 h5 = INV ? make_float2(s * (g5.x - g5.y), s * (g5.y + g5.x))
                    : make_float2(s * (g5.x + g5.y), s * (g5.y - g5.x));
    float2 h6 = mulmi<INV>(g6);
    float2 h7 = INV ? make_float2(-s * (g7.x + g7.y), -s * (g7.y - g7.x))
                    : make_float2(-s * (g7.x - g7.y), -s * (g7.x + g7.y));
    c[0] = cadd(g0, g4); c[4] = csub(g0, g4);
    c[1] = cadd(g1, h5); c[5] = csub(g1, h5);
    c[2] = cadd(g2, h6); c[6] = csub(g2, h6);
    c[3] = cadd(g3, h7); c[7] = csub(g3, h7);
}
template<bool INV> __device__ __forceinline__ void dft4(float2* c) {
    float2 a0 = cadd(c[0], c[2]), a1 = csub(c[0], c[2]);
    float2 a2 = cadd(c[1], c[3]), a3 = csub(c[1], c[3]);
    float2 t = mulmi<INV>(a3);
    c[0] = cadd(a0, a2); c[2] = csub(a0, a2); c[1] = cadd(a1, t); c[3] = csub(a1, t);
}
// c[r] *= w^r, tree-form powers
__device__ __forceinline__ void twpow8(float2* c, float2 w) {
    float2 w2 = cmulf(w, w);
    c[1] = cmulf(c[1], w);
    c[2] = cmulf(c[2], w2);
    float2 w3 = cmulf(w2, w);
    float2 w4 = cmulf(w2, w2);
    c[3] = cmulf(c[3], w3);
    c[4] = cmulf(c[4], w4);
    c[5] = cmulf(c[5], cmulf(w4, w));
    c[6] = cmulf(c[6], cmulf(w4, w2));
    c[7] = cmulf(c[7], cmulf(w4, w3));
}

// 512-point radix-8 Stockham FFT, IN PLACE in one 648-entry buffer S.
// 64 butterflies/stage across 2 warps (bb in [0,64)); read-all/BARCOL/write-all per stage.
// Natural input in S[0..512); natural output in S[0..512).
template<bool INV>
__device__ __forceinline__ void fft512_ip(float2* S, float2 w1, int bb, int col) {
    const int lane = bb & 31;
    float2 wst2 = shfl_c(w1, lane & ~7);     // exp(-2pi i 8*(bb>>3)/512)
    if (INV) { w1.y = -w1.y; wst2.y = -wst2.y; }
    float2 c[8];
    // stage 1: m=1, natural -> MAP
#pragma unroll
    for (int t = 0; t < 8; ++t) c[t] = S[bb + 64 * t];
    dft8<INV>(c);
    twpow8(c, w1);
    BARCOL(col + 1);
#pragma unroll
    for (int r = 0; r < 8; ++r) S[MAP(8 * bb + r)] = c[r];
    BARCOL(col + 1);
    // stage 2: m=8, MAP -> MAP
#pragma unroll
    for (int t = 0; t < 8; ++t) c[t] = S[MAP(bb + 64 * t)];
    {
        int j = bb >> 3, k = bb & 7;
        dft8<INV>(c);
        twpow8(c, wst2);
        BARCOL(col + 1);
#pragma unroll
        for (int r = 0; r < 8; ++r) S[MAP(k + 64 * j + 8 * r)] = c[r];
    }
    BARCOL(col + 1);
    // stage 3: m=64, no twiddle, MAP -> natural
#pragma unroll
    for (int t = 0; t < 8; ++t) c[t] = S[MAP(bb + 64 * t)];
    dft8<INV>(c);
    BARCOL(col + 1);
#pragma unroll
    for (int r = 0; r < 8; ++r) S[bb + 64 * r] = c[r];
}

// Per-warp forward 256-FFT (8,8,4): input from global (coalesced), output X natural.
// Y is a 288-float2 per-warp scratch (in-place middle stage, reg-staged).
__device__ __forceinline__ void fwd256(const float2* __restrict__ gsrc, float2* X, float2* Y,
                                       float2 wm1, float2 wm2, int lane) {
    {   // stage 1: m=1, global -> Y(map)
        float2 c[8];
#pragma unroll
        for (int t = 0; t < 8; ++t) c[t] = gsrc[lane + 32 * t];
        dft8<false>(c);
        twpow8(c, wm1);
#pragma unroll
        for (int r = 0; r < 8; ++r) Y[MAP(8 * lane + r)] = c[r];
    }
    __syncwarp();
    {   // stage 2: m=8, in-place in Y (read all, syncwarp, write all)
        int j = lane >> 3, k = lane & 7;
        float2 c[8];
#pragma unroll
        for (int t = 0; t < 8; ++t) c[t] = Y[MAP(lane + 32 * t)];
        __syncwarp();
        dft8<false>(c);
        twpow8(c, wm2);
#pragma unroll
        for (int r = 0; r < 8; ++r) Y[MAP(k + 64 * j + 8 * r)] = c[r];
    }
    __syncwarp();
#pragma unroll 1
    for (int h = 0; h < 2; ++h) {   // stage 3: radix-4, m=64, Y(map) -> X(nat)
        int b = lane + 32 * h;
        float2 c[4];
#pragma unroll
        for (int t = 0; t < 4; ++t) c[t] = Y[MAP(b + 64 * t)];
        dft4<false>(c);
#pragma unroll
        for (int r = 0; r < 4; ++r) X[b + 64 * r] = c[r];
    }
    __syncwarp();
}

// ---------------- setup kernel (gates + tail + global max in one launch) ----------------

__global__ void k_pre(const float* __restrict__ ctrl, const float4* __restrict__ z4, int n4,
                      float* __restrict__ outf, long long tail_pos, int tail_on) {
    if (blockIdx.x == 0) {
        int t = threadIdx.x;
        if (t < HB) {
            float s = 1.f / (1.f + expf(-ctrl[t * 3 + 0]));
            float r = 1.f / (1.f + expf(-ctrl[t * 3 + 1]));
            g_gates[t] = make_float2(s, r);
        }
        if (tail_on && t < 65) outf[tail_pos + t] = (t == 64) ? 1.f : 0.f;
    }
    __shared__ float sm[8];
    float m = 0.f;
    for (int i = blockIdx.x * blockDim.x + threadIdx.x; i < n4; i += gridDim.x * blockDim.x) {
        float4 v = z4[i];
        m = fmaxf(m, fmaxf(fmaxf(fabsf(v.x), fabsf(v.y)), fmaxf(fabsf(v.z), fabsf(v.w))));
    }
#pragma unroll
    for (int o = 16; o; o >>= 1) m = fmaxf(m, __shfl_xor_sync(0xffffffffu, m, o));
    if ((threadIdx.x & 31) == 0) sm[threadIdx.x >> 5] = m;
    __syncthreads();
    if (threadIdx.x < 8) {
        m = sm[threadIdx.x];
#pragma unroll
        for (int o = 4; o; o >>= 1) m = fmaxf(m, __shfl_xor_sync(0xffu, m, o));
        if (threadIdx.x == 0) atomicMax(&g_maxbits, __float_as_uint(m));
    }
}

// ---------------- FFT passes ----------------
// x[n], n = n1*256 + n2.  Spectrum stored permuted: A[k1*256 + n2] after pass 1.

extern __shared__ float2 smem[];

// F1 (512 threads, 4 blocks/SM): per 8 columns n2, in-place 512-FFT over n1,
// apply W_N^{n2*k1}, write bufA.
__global__ __launch_bounds__(512, 4) void k_fwd1(const float* __restrict__ z,
                                                 const float* __restrict__ tr,
                                                 float* __restrict__ outf,
                                                 float2* __restrict__ outc,
                                                 int nt_mode) {
    const int w = threadIdx.x >> 5, lane = threadIdx.x & 31;
    const int col = w >> 1;                 // column 0..7, 2 warps per column
    const int bb = lane + 32 * (w & 1);     // butterfly index 0..63
    float2* S = smem + col * CSS;
    const float2 w1 = twu(bb << 8);         // exp(-2pi i bb/512)
    const int row = blockIdx.y;
    const int n2base = blockIdx.x * 8;
    const int tid = threadIdx.x;

    const float mx = __uint_as_float(g_maxbits);
    const float scale = 1.f / (mx + 1e-6f);
    const float st_g = g_gates[row].x;
    const size_t rb = (size_t)row * HDIM;
    const size_t BD = (size_t)HB * HDIM;

    const float4* z4 = (const float4*)(z + rb + n2base);
    const float4* t4 = (const float4*)(tr + rb + n2base);
    float4* nt4 = (float4*)(outf + BD + rb + n2base);
#pragma unroll
    for (int i = tid; i < 1024; i += 512) {
        int n1 = i >> 1, h = i & 1;
        int f4i = n1 * 64 + h;
        float4 zv = z4[f4i], tv = t4[f4i];
        float zn0 = zv.x * scale, zn1 = zv.y * scale, zn2 = zv.z * scale, zn3 = zv.w * scale;
        float n0 = tv.x + st_g * zn0, n1v = tv.y + st_g * zn1;
        float n2v = tv.z + st_g * zn2, n3 = tv.w + st_g * zn3;
        int jq = h * 4;
        smem[(jq + 0) * CSS + n1] = make_float2(n0, zn0);
        smem[(jq + 1) * CSS + n1] = make_float2(n1v, zn1);
        smem[(jq + 2) * CSS + n1] = make_float2(n2v, zn2);
        smem[(jq + 3) * CSS + n1] = make_float2(n3, zn3);
        if (nt_mode == 1) {
            nt4[f4i] = make_float4(n0, n1v, n2v, n3);
        } else if (nt_mode == 2) {
            size_t gidx = BD + rb + (size_t)n1 * 256 + n2base + jq;
            outc[gidx + 0] = make_float2(n0, 0.f);
            outc[gidx + 1] = make_float2(n1v, 0.f);
            outc[gidx + 2] = make_float2(n2v, 0.f);
            outc[gidx + 3] = make_float2(n3, 0.f);
        }
    }
    __syncthreads();
    fft512_ip<false>(S, w1, bb, col);       // result natural in S
    __syncthreads();
    {   // output + four-step twiddle, incremental per thread
        const int j = tid & 7, k1_0 = tid >> 3;
        const int n2 = n2base + j;
        float2 twc = twu(n2 * k1_0);
        const float2 stp = twu(64 * n2);
        const float2* Sp = smem + j * CSS;
#pragma unroll
        for (int m = 0; m < 8; ++m) {
            int k1 = k1_0 + 64 * m;
            g_bufA[rb + (k1 << 8) + n2] = cmulf(Sp[k1], twc);
            twc = cmulf(twc, stp);
        }
    }
}

// MID (fused fwd2 + Hermitian pointwise + row-pair pack + inv1), 256 threads.
// Block = 8 spectral columns (4 mirror pairs) x 1 row pair; each warp owns one column.
__global__ __launch_bounds__(256) void k_mid() {
    const int w = threadIdx.x >> 5, lane = threadIdx.x & 31;
    float2* X0 = smem + w * MWS;            // 256 natural
    float2* X1 = X0 + 256;                  // 256 natural
    float2* Y  = X0 + 512;                  // 288 scratch (MAP)
    const float2 wm1 = twu(lane << 9);      // exp(-2pi i lane/256)
    const float2 wm2 = shfl_c(wm1, lane & ~7);

    const int rp = blockIdx.y;              // row pair [0,32)
    const int bx = blockIdx.x;              // [0,64)
    const int kbase = bx * 4 + (w >> 1);
    int k1 = (w & 1) ? ((512 - kbase) & 511) : kbase;
    if (bx == 0 && w == 1) k1 = 256;        // mir(0) dup -> self-mirrored 256
    const bool selfm = (k1 == 0) | (k1 == 256);
    const float2* Xp0 = smem + (selfm ? w : (w ^ 1)) * MWS;
    const float2* Xp1 = Xp0 + 256;
    const size_t row0 = (size_t)(rp * 2) * HDIM;
    const size_t c1off = (size_t)k1 << 8;

    fwd256(g_bufA + row0 + c1off, X0, Y, wm1, wm2, lane);
    fwd256(g_bufA + row0 + HDIM + c1off, X1, Y, wm1, wm2, lane);
    __syncthreads();                        // all warps' X0/X1 visible for mirror reads

    // split + product + pack G = P0 + i*P1 in registers
    const float fac0 = g_gates[rp * 2].y * (1.f / (float)HDIM);
    const float fac1 = g_gates[rp * 2 + 1].y * (1.f / (float)HDIM);
    float2 q[8];
#pragma unroll
    for (int t = 0; t < 8; ++t) {
        int k2 = lane + 32 * t;
        int k2m = (k1 == 0) ? ((256 - k2) & 255) : (255 - k2);
        float2 C0 = X0[k2], Cm0 = Xp0[k2m];
        float2 NT0 = make_float2(0.5f * (C0.x + Cm0.x), 0.5f * (C0.y - Cm0.y));
        float2 Z0  = make_float2(0.5f * (C0.y + Cm0.y), -0.5f * (C0.x - Cm0.x));
        float2 P0  = cmulf(NT0, make_float2(Z0.x, -Z0.y));
        float2 C1 = X1[k2], Cm1 = Xp1[k2m];
        float2 NT1 = make_float2(0.5f * (C1.x + Cm1.x), 0.5f * (C1.y - Cm1.y));
        float2 Z1  = make_float2(0.5f * (C1.y + Cm1.y), -0.5f * (C1.x - Cm1.x));
        float2 P1  = cmulf(NT1, make_float2(Z1.x, -Z1.y));
        q[t] = make_float2(fac0 * P0.x - fac1 * P1.y, fac0 * P0.y + fac1 * P1.x);
    }

    // inverse 256-FFT on G
    dft8<true>(q);                          // stage 1: m=1, regs -> Y(map)
    { float2 wv = wm1; wv.y = -wv.y; twpow8(q, wv); }
#pragma unroll
    for (int r = 0; r < 8; ++r) Y[MAP(8 * lane + r)] = q[r];
    __syncwarp();
    {   // stage 2: m=8, in-place in Y
        int j = lane >> 3, k = lane & 7;
        float2 c[8];
#pragma unroll
        for (int t = 0; t < 8; ++t) c[t] = Y[MAP(lane + 32 * t)];
        __syncwarp();
        dft8<true>(c);
        float2 wv = wm2; wv.y = -wv.y;
        twpow8(c, wv);
#pragma unroll
        for (int r = 0; r < 8; ++r) Y[MAP(k + 64 * j + 8 * r)] = c[r];
    }
    __syncwarp();
    // stage 3: radix-4 -> global with conj four-step twiddle, incremental
    float2 stpc = twu(64 * k1); stpc.y = -stpc.y;
    const size_t gb = (size_t)rp * HDIM + c1off;
#pragma unroll 1
    for (int h = 0; h < 2; ++h) {
        int b = lane + 32 * h;
        float2 c[4];
#pragma unroll
        for (int t = 0; t < 4; ++t) c[t] = Y[MAP(b + 64 * t)];
        dft4<true>(c);
        float2 twc = twu(b * k1); twc.y = -twc.y;
#pragma unroll
        for (int r = 0; r < 4; ++r) {
            int n2 = b + 64 * r;
            g_bufP[gb + n2] = cmulf(c[r], twc);
            twc = cmulf(twc, stpc);
        }
    }
}

// I2 (512 threads, 4 blocks/SM): per 8 columns n2, in-place inverse 512-FFT over k1
// on packed G. Output: Re -> row 2*rp, Im -> row 2*rp+1.
__global__ __launch_bounds__(512, 4) void k_inv2(float* __restrict__ outf,
                                                 float2* __restrict__ outc, int read_mode) {
    const int w = threadIdx.x >> 5, lane = threadIdx.x & 31;
    const int col = w >> 1;
    const int bb = lane + 32 * (w & 1);
    float2* S = smem + col * CSS;
    const float2 w1 = twu(bb << 8);
    const int rp = blockIdx.y;              // row pair
    const int n2base = blockIdx.x * 8;
    const int tid = threadIdx.x;
    const size_t pb = (size_t)rp * HDIM;
    const size_t r0 = (size_t)(rp * 2) * HDIM;
    const size_t r1 = r0 + HDIM;

    {   // float4 gather of bufP (2 consecutive float2 per load)
        const float4* p4 = (const float4*)(g_bufP + pb + n2base);
#pragma unroll
        for (int i = tid; i < 2048; i += 512) {
            int jq = i & 3, k1 = i >> 2;
            float4 v = p4[(k1 << 7) + jq];
            smem[(2 * jq) * CSS + k1]     = make_float2(v.x, v.y);
            smem[(2 * jq + 1) * CSS + k1] = make_float2(v.z, v.w);
        }
    }
    __syncthreads();
    fft512_ip<true>(S, w1, bb, col);        // result natural in S
    __syncthreads();
    if (read_mode == 2) {
        float4* o40 = (float4*)(outf + r0 + n2base);
        float4* o41 = (float4*)(outf + r1 + n2base);
#pragma unroll
        for (int i = tid; i < 1024; i += 512) {
            int n1 = i >> 1, h = i & 1;
            int jq = h * 4;
            float2 v0 = smem[(jq + 0) * CSS + n1];
            float2 v1 = smem[(jq + 1) * CSS + n1];
            float2 v2 = smem[(jq + 2) * CSS + n1];
            float2 v3 = smem[(jq + 3) * CSS + n1];
            o40[n1 * 64 + h] = make_float4(v0.x, v1.x, v2.x, v3.x);
            o41[n1 * 64 + h] = make_float4(v0.y, v1.y, v2.y, v3.y);
        }
    } else if (read_mode == 1) {
        for (int i = tid; i < 4096; i += 512) {
            int n1 = i >> 3, j = i & 7;
            float2 v = smem[j * CSS + n1];
            size_t off = (size_t)(n1 << 8) + n2base + j;
            outc[r0 + off] = make_float2(v.x, 0.f);
            outc[r1 + off] = make_float2(v.y, 0.f);
        }
    }
}

// ---------------- launcher ----------------

extern "C" void kernel_launch(void* const* d_in, const int* in_sizes, int n_in,
                              void* d_out, int out_size) {
    const float* big[2] = {nullptr, nullptr};
    const float* ctrl = nullptr;
    int nb = 0;
    for (int i = 0; i < n_in; ++i) {
        if (in_sizes[i] == HB * 3) ctrl = (const float*)d_in[i];
        else if (in_sizes[i] == HB * HDIM && nb < 2) big[nb++] = (const float*)d_in[i];
    }
    if (nb != 2 || !ctrl) return;
    const float* z  = big[0];
    const float* tr = big[1];

    // SAFETY: every output store lies within out_size*4 bytes (minimal element size).
    const long long BD = (long long)HB * HDIM;
    long long os = out_size;
    int read_mode = 0, nt_mode = 0, tail_on = 0;
    long long tail_pos = 0;
    if (os >= 4 * BD) {              // complex-interleaved layout
        read_mode = 1; nt_mode = 2;
        tail_pos = 4 * BD; tail_on = (os >= 4 * BD + 65);
    } else if (os >= 2 * BD) {       // float32 real-part layout (os = 2BD+65)
        read_mode = 2; nt_mode = 1;
        tail_pos = 2 * BD; tail_on = (os >= 2 * BD + 65);
    } else if (os >= BD) {
        read_mode = 2;
    }

    float*  outf = (float*)d_out;
    float2* outc = (float2*)d_out;

    const int S1 = (8 * CSS) * (int)sizeof(float2);      // 42.0 KB
    const int SM = (8 * MWS) * (int)sizeof(float2);      // 51.2 KB
    cudaFuncSetAttribute(k_fwd1, cudaFuncAttributeMaxDynamicSharedMemorySize, S1);
    cudaFuncSetAttribute(k_inv2, cudaFuncAttributeMaxDynamicSharedMemorySize, S1);
    cudaFuncSetAttribute(k_mid,  cudaFuncAttributeMaxDynamicSharedMemorySize, SM);

    k_pre<<<1024, 256>>>(ctrl, (const float4*)z, (HB * HDIM) / 4, outf, tail_pos, tail_on);
    k_fwd1<<<dim3(HN2 / 8, HB), 512, S1>>>(z, tr, outf, outc, nt_mode);
    k_mid<<<dim3(HN1 / 8, HB / 2), 256, SM>>>();
    k_inv2<<<dim3(HN2 / 8, HB / 2), 512, S1>>>(outf, outc, read_mode);
}

// round 17
// speedup vs baseline: 1.1348x; 1.1348x over previous
#include <cuda_runtime.h>
#include <math.h>

#define HB   64
#define HDIM 131072
#define HN1  512
#define HN2  256
// Column stride (float2) for in-place 512-FFT. MUST NOT be ≡0 mod 16 float2
// (32 4B banks): 658 -> 1316 words, 1316 mod 32 = 4 (bank-staggered columns).
// (R16 used 656 -> 1312 ≡ 0 mod 32: every column aliased the same banks, 4-way
// conflicts in all transpose phases — that was the regression.)
#define CSS  658
#define MAP(i) ((i) + ((i) >> 3))   // padded intermediate layout (conflict reduction)
#define MWS  800             // k_mid per-warp smem: X0[256] X1[256] Y[288]

#define BARCOL(id) asm volatile("bar.sync %0, %1;" :: "r"(id), "r"(64) : "memory")

// Static device scratch (allowed; no runtime allocation)
static __device__ float2 g_bufA[(size_t)HB * HDIM];        // 64 MB  fwd stage-1 out
static __device__ float2 g_bufP[(size_t)(HB / 2) * HDIM];  // 32 MB  packed G per row pair
static __device__ unsigned g_maxbits;                      // zero-init; atomicMax idempotent
static __device__ float2 g_gates[HB];                      // (store, retrieve) per row

__device__ __forceinline__ float2 cmulf(float2 a, float2 b) {
    return make_float2(fmaf(a.x, b.x, -a.y * b.y), fmaf(a.x, b.y, a.y * b.x));
}
__device__ __forceinline__ float2 cadd(float2 a, float2 b) { return make_float2(a.x + b.x, a.y + b.y); }
__device__ __forceinline__ float2 csub(float2 a, float2 b) { return make_float2(a.x - b.x, a.y - b.y); }
template<bool INV> __device__ __forceinline__ float2 mulmi(float2 v) {   // *(−i) fwd, *(+i) inv
    return INV ? make_float2(-v.y, v.x) : make_float2(v.y, -v.x);
}
__device__ __forceinline__ float2 shfl_c(float2 v, int src) {
    return make_float2(__shfl_sync(0xffffffffu, v.x, src), __shfl_sync(0xffffffffu, v.y, src));
}
// e^{-2*pi*i * a / HDIM} in registers; a < 2^24 so (float)a exact, /65536 exact.
__device__ __forceinline__ float2 twu(int a) {
    float s, c;
    sincospif((float)a * (1.0f / 65536.0f), &s, &c);
    return make_float2(c, -s);
}

// 8-point DFT in registers, natural in/out order.
template<bool INV> __device__ __forceinline__ void dft8(float2* c) {
    const float s = 0.70710678118654752440f;
    float2 e0 = c[0], e1 = c[4], e2 = c[2], e3 = c[6], e4 = c[1], e5 = c[5], e6 = c[3], e7 = c[7];
    float2 f0 = cadd(e0, e1), f1 = csub(e0, e1), f2 = cadd(e2, e3), f3 = csub(e2, e3);
    float2 f4 = cadd(e4, e5), f5 = csub(e4, e5), f6 = cadd(e6, e7), f7 = csub(e6, e7);
    float2 t3 = mulmi<INV>(f3), t7 = mulmi<INV>(f7);
    float2 g0 = cadd(f0, f2), g2 = csub(f0, f2), g1 = cadd(f1, t3), g3 = csub(f1, t3);
    float2 g4 = cadd(f4, f6), g6 = csub(f4, f6), g5 = cadd(f5, t7), g7 = csub(f5, t7);
    float2 h5 = INV ? make_float2(s * (g5.x - g5.y), s * (g5.y + g5.x))
                    : make_float2(s * (g5.x + g5.y), s * (g5.y - g5.x));
    float2 h6 = mulmi<INV>(g6);
    float2 h7 = INV ? make_float2(-s * (g7.x + g7.y), -s * (g7.y - g7.x))
                    : make_float2(-s * (g7.x - g7.y), -s * (g7.x + g7.y));
    c[0] = cadd(g0, g4); c[4] = csub(g0, g4);
    c[1] = cadd(g1, h5); c[5] = csub(g1, h5);
    c[2] = cadd(g2, h6); c[6] = csub(g2, h6);
    c[3] = cadd(g3, h7); c[7] = csub(g3, h7);
}
template<bool INV> __device__ __forceinline__ void dft4(float2* c) {
    float2 a0 = cadd(c[0], c[2]), a1 = csub(c[0], c[2]);
    float2 a2 = cadd(c[1], c[3]), a3 = csub(c[1], c[3]);
    float2 t = mulmi<INV>(a3);
    c[0] = cadd(a0, a2); c[2] = csub(a0, a2); c[1] = cadd(a1, t); c[3] = csub(a1, t);
}
// c[r] *= w^r, tree-form powers
__device__ __forceinline__ void twpow8(float2* c, float2 w) {
    float2 w2 = cmulf(w, w);
    c[1] = cmulf(c[1], w);
    c[2] = cmulf(c[2], w2);
    float2 w3 = cmulf(w2, w);
    float2 w4 = cmulf(w2, w2);
    c[3] = cmulf(c[3], w3);
    c[4] = cmulf(c[4], w4);
    c[5] = cmulf(c[5], cmulf(w4, w));
    c[6] = cmulf(c[6], cmulf(w4, w2));
    c[7] = cmulf(c[7], cmulf(w4, w3));
}

// 512-point radix-8 Stockham FFT, IN PLACE in one 648-entry buffer S.
// 64 butterflies/stage across 2 warps (bb in [0,64)); read-all/BARCOL/write-all per stage.
// Natural input in S[0..512); natural output in S[0..512).
template<bool INV>
__device__ __forceinline__ void fft512_ip(float2* S, float2 w1, int bb, int col) {
    const int lane = bb & 31;
    float2 wst2 = shfl_c(w1, lane & ~7);     // exp(-2pi i 8*(bb>>3)/512)
    if (INV) { w1.y = -w1.y; wst2.y = -wst2.y; }
    float2 c[8];
    // stage 1: m=1, natural -> MAP
#pragma unroll
    for (int t = 0; t < 8; ++t) c[t] = S[bb + 64 * t];
    dft8<INV>(c);
    twpow8(c, w1);
    BARCOL(col + 1);
#pragma unroll
    for (int r = 0; r < 8; ++r) S[MAP(8 * bb + r)] = c[r];
    BARCOL(col + 1);
    // stage 2: m=8, MAP -> MAP
#pragma unroll
    for (int t = 0; t < 8; ++t) c[t] = S[MAP(bb + 64 * t)];
    {
        int j = bb >> 3, k = bb & 7;
        dft8<INV>(c);
        twpow8(c, wst2);
        BARCOL(col + 1);
#pragma unroll
        for (int r = 0; r < 8; ++r) S[MAP(k + 64 * j + 8 * r)] = c[r];
    }
    BARCOL(col + 1);
    // stage 3: m=64, no twiddle, MAP -> natural
#pragma unroll
    for (int t = 0; t < 8; ++t) c[t] = S[MAP(bb + 64 * t)];
    dft8<INV>(c);
    BARCOL(col + 1);
#pragma unroll
    for (int r = 0; r < 8; ++r) S[bb + 64 * r] = c[r];
}

// Per-warp forward 256-FFT (8,8,4): input from global (coalesced), output X natural.
// Y is a 288-float2 per-warp scratch (in-place middle stage, reg-staged).
__device__ __forceinline__ void fwd256(const float2* __restrict__ gsrc, float2* X, float2* Y,
                                       float2 wm1, float2 wm2, int lane) {
    {   // stage 1: m=1, global -> Y(map)
        float2 c[8];
#pragma unroll
        for (int t = 0; t < 8; ++t) c[t] = gsrc[lane + 32 * t];
        dft8<false>(c);
        twpow8(c, wm1);
#pragma unroll
        for (int r = 0; r < 8; ++r) Y[MAP(8 * lane + r)] = c[r];
    }
    __syncwarp();
    {   // stage 2: m=8, in-place in Y (read all, syncwarp, write all)
        int j = lane >> 3, k = lane & 7;
        float2 c[8];
#pragma unroll
        for (int t = 0; t < 8; ++t) c[t] = Y[MAP(lane + 32 * t)];
        __syncwarp();
        dft8<false>(c);
        twpow8(c, wm2);
#pragma unroll
        for (int r = 0; r < 8; ++r) Y[MAP(k + 64 * j + 8 * r)] = c[r];
    }
    __syncwarp();
#pragma unroll 1
    for (int h = 0; h < 2; ++h) {   // stage 3: radix-4, m=64, Y(map) -> X(nat)
        int b = lane + 32 * h;
        float2 c[4];
#pragma unroll
        for (int t = 0; t < 4; ++t) c[t] = Y[MAP(b + 64 * t)];
        dft4<false>(c);
#pragma unroll
        for (int r = 0; r < 4; ++r) X[b + 64 * r] = c[r];
    }
    __syncwarp();
}

// ---------------- setup kernel (gates + tail + global max in one launch) ----------------

__global__ void k_pre(const float* __restrict__ ctrl, const float4* __restrict__ z4, int n4,
                      float* __restrict__ outf, long long tail_pos, int tail_on) {
    if (blockIdx.x == 0) {
        int t = threadIdx.x;
        if (t < HB) {
            float s = 1.f / (1.f + expf(-ctrl[t * 3 + 0]));
            float r = 1.f / (1.f + expf(-ctrl[t * 3 + 1]));
            g_gates[t] = make_float2(s, r);
        }
        if (tail_on && t < 65) outf[tail_pos + t] = (t == 64) ? 1.f : 0.f;
    }
    __shared__ float sm[8];
    float m = 0.f;
    for (int i = blockIdx.x * blockDim.x + threadIdx.x; i < n4; i += gridDim.x * blockDim.x) {
        float4 v = z4[i];
        m = fmaxf(m, fmaxf(fmaxf(fabsf(v.x), fabsf(v.y)), fmaxf(fabsf(v.z), fabsf(v.w))));
    }
#pragma unroll
    for (int o = 16; o; o >>= 1) m = fmaxf(m, __shfl_xor_sync(0xffffffffu, m, o));
    if ((threadIdx.x & 31) == 0) sm[threadIdx.x >> 5] = m;
    __syncthreads();
    if (threadIdx.x < 8) {
        m = sm[threadIdx.x];
#pragma unroll
        for (int o = 4; o; o >>= 1) m = fmaxf(m, __shfl_xor_sync(0xffu, m, o));
        if (threadIdx.x == 0) atomicMax(&g_maxbits, __float_as_uint(m));
    }
}

// ---------------- FFT passes ----------------
// x[n], n = n1*256 + n2.  Spectrum stored permuted: A[k1*256 + n2] after pass 1.

extern __shared__ float2 smem[];

// F1 (512 threads, 4 blocks/SM): per 8 columns n2, in-place 512-FFT over n1,
// apply W_N^{n2*k1}, write bufA.
__global__ __launch_bounds__(512, 4) void k_fwd1(const float* __restrict__ z,
                                                 const float* __restrict__ tr,
                                                 float* __restrict__ outf,
                                                 float2* __restrict__ outc,
                                                 int nt_mode) {
    const int w = threadIdx.x >> 5, lane = threadIdx.x & 31;
    const int col = w >> 1;                 // column 0..7, 2 warps per column
    const int bb = lane + 32 * (w & 1);     // butterfly index 0..63
    float2* S = smem + col * CSS;
    const float2 w1 = twu(bb << 8);         // exp(-2pi i bb/512)
    const int row = blockIdx.y;
    const int n2base = blockIdx.x * 8;
    const int tid = threadIdx.x;

    const float mx = __uint_as_float(g_maxbits);
    const float scale = 1.f / (mx + 1e-6f);
    const float st_g = g_gates[row].x;
    const size_t rb = (size_t)row * HDIM;
    const size_t BD = (size_t)HB * HDIM;

    const float4* z4 = (const float4*)(z + rb + n2base);
    const float4* t4 = (const float4*)(tr + rb + n2base);
    float4* nt4 = (float4*)(outf + BD + rb + n2base);
#pragma unroll
    for (int i = tid; i < 1024; i += 512) {
        int n1 = i >> 1, h = i & 1;
        int f4i = n1 * 64 + h;
        float4 zv = z4[f4i], tv = t4[f4i];
        float zn0 = zv.x * scale, zn1 = zv.y * scale, zn2 = zv.z * scale, zn3 = zv.w * scale;
        float n0 = tv.x + st_g * zn0, n1v = tv.y + st_g * zn1;
        float n2v = tv.z + st_g * zn2, n3 = tv.w + st_g * zn3;
        int jq = h * 4;
        smem[(jq + 0) * CSS + n1] = make_float2(n0, zn0);
        smem[(jq + 1) * CSS + n1] = make_float2(n1v, zn1);
        smem[(jq + 2) * CSS + n1] = make_float2(n2v, zn2);
        smem[(jq + 3) * CSS + n1] = make_float2(n3, zn3);
        if (nt_mode == 1) {
            nt4[f4i] = make_float4(n0, n1v, n2v, n3);
        } else if (nt_mode == 2) {
            size_t gidx = BD + rb + (size_t)n1 * 256 + n2base + jq;
            outc[gidx + 0] = make_float2(n0, 0.f);
            outc[gidx + 1] = make_float2(n1v, 0.f);
            outc[gidx + 2] = make_float2(n2v, 0.f);
            outc[gidx + 3] = make_float2(n3, 0.f);
        }
    }
    __syncthreads();
    fft512_ip<false>(S, w1, bb, col);       // result natural in S
    __syncthreads();
    {   // output + four-step twiddle, incremental per thread
        const int j = tid & 7, k1_0 = tid >> 3;
        const int n2 = n2base + j;
        float2 twc = twu(n2 * k1_0);
        const float2 stp = twu(64 * n2);
        const float2* Sp = smem + j * CSS;
#pragma unroll
        for (int m = 0; m < 8; ++m) {
            int k1 = k1_0 + 64 * m;
            g_bufA[rb + (k1 << 8) + n2] = cmulf(Sp[k1], twc);
            twc = cmulf(twc, stp);
        }
    }
}

// MID (fused fwd2 + Hermitian pointwise + row-pair pack + inv1), 256 threads.
// Block = 8 spectral columns (4 mirror pairs) x 1 row pair; each warp owns one column.
__global__ __launch_bounds__(256) void k_mid() {
    const int w = threadIdx.x >> 5, lane = threadIdx.x & 31;
    float2* X0 = smem + w * MWS;            // 256 natural
    float2* X1 = X0 + 256;                  // 256 natural
    float2* Y  = X0 + 512;                  // 288 scratch (MAP)
    const float2 wm1 = twu(lane << 9);      // exp(-2pi i lane/256)
    const float2 wm2 = shfl_c(wm1, lane & ~7);

    const int rp = blockIdx.y;              // row pair [0,32)
    const int bx = blockIdx.x;              // [0,64)
    const int kbase = bx * 4 + (w >> 1);
    int k1 = (w & 1) ? ((512 - kbase) & 511) : kbase;
    if (bx == 0 && w == 1) k1 = 256;        // mir(0) dup -> self-mirrored 256
    const bool selfm = (k1 == 0) | (k1 == 256);
    const float2* Xp0 = smem + (selfm ? w : (w ^ 1)) * MWS;
    const float2* Xp1 = Xp0 + 256;
    const size_t row0 = (size_t)(rp * 2) * HDIM;
    const size_t c1off = (size_t)k1 << 8;

    fwd256(g_bufA + row0 + c1off, X0, Y, wm1, wm2, lane);
    fwd256(g_bufA + row0 + HDIM + c1off, X1, Y, wm1, wm2, lane);
    __syncthreads();                        // all warps' X0/X1 visible for mirror reads

    // split + product + pack G = P0 + i*P1 in registers
    const float fac0 = g_gates[rp * 2].y * (1.f / (float)HDIM);
    const float fac1 = g_gates[rp * 2 + 1].y * (1.f / (float)HDIM);
    float2 q[8];
#pragma unroll
    for (int t = 0; t < 8; ++t) {
        int k2 = lane + 32 * t;
        int k2m = (k1 == 0) ? ((256 - k2) & 255) : (255 - k2);
        float2 C0 = X0[k2], Cm0 = Xp0[k2m];
        float2 NT0 = make_float2(0.5f * (C0.x + Cm0.x), 0.5f * (C0.y - Cm0.y));
        float2 Z0  = make_float2(0.5f * (C0.y + Cm0.y), -0.5f * (C0.x - Cm0.x));
        float2 P0  = cmulf(NT0, make_float2(Z0.x, -Z0.y));
        float2 C1 = X1[k2], Cm1 = Xp1[k2m];
        float2 NT1 = make_float2(0.5f * (C1.x + Cm1.x), 0.5f * (C1.y - Cm1.y));
        float2 Z1  = make_float2(0.5f * (C1.y + Cm1.y), -0.5f * (C1.x - Cm1.x));
        float2 P1  = cmulf(NT1, make_float2(Z1.x, -Z1.y));
        q[t] = make_float2(fac0 * P0.x - fac1 * P1.y, fac0 * P0.y + fac1 * P1.x);
    }

    // inverse 256-FFT on G
    dft8<true>(q);                          // stage 1: m=1, regs -> Y(map)
    { float2 wv = wm1; wv.y = -wv.y; twpow8(q, wv); }
#pragma unroll
    for (int r = 0; r < 8; ++r) Y[MAP(8 * lane + r)] = q[r];
    __syncwarp();
    {   // stage 2: m=8, in-place in Y
        int j = lane >> 3, k = lane & 7;
        float2 c[8];
#pragma unroll
        for (int t = 0; t < 8; ++t) c[t] = Y[MAP(lane + 32 * t)];
        __syncwarp();
        dft8<true>(c);
        float2 wv = wm2; wv.y = -wv.y;
        twpow8(c, wv);
#pragma unroll
        for (int r = 0; r < 8; ++r) Y[MAP(k + 64 * j + 8 * r)] = c[r];
    }
    __syncwarp();
    // stage 3: radix-4 -> global with conj four-step twiddle, incremental
    float2 stpc = twu(64 * k1); stpc.y = -stpc.y;
    const size_t gb = (size_t)rp * HDIM + c1off;
#pragma unroll 1
    for (int h = 0; h < 2; ++h) {
        int b = lane + 32 * h;
        float2 c[4];
#pragma unroll
        for (int t = 0; t < 4; ++t) c[t] = Y[MAP(b + 64 * t)];
        dft4<true>(c);
        float2 twc = twu(b * k1); twc.y = -twc.y;
#pragma unroll
        for (int r = 0; r < 4; ++r) {
            int n2 = b + 64 * r;
            g_bufP[gb + n2] = cmulf(c[r], twc);
            twc = cmulf(twc, stpc);
        }
    }
}

// I2 (512 threads, 4 blocks/SM): per 8 columns n2, in-place inverse 512-FFT over k1
// on packed G. Output: Re -> row 2*rp, Im -> row 2*rp+1.
__global__ __launch_bounds__(512, 4) void k_inv2(float* __restrict__ outf,
                                                 float2* __restrict__ outc, int read_mode) {
    const int w = threadIdx.x >> 5, lane = threadIdx.x & 31;
    const int col = w >> 1;
    const int bb = lane + 32 * (w & 1);
    float2* S = smem + col * CSS;
    const float2 w1 = twu(bb << 8);
    const int rp = blockIdx.y;              // row pair
    const int n2base = blockIdx.x * 8;
    const int tid = threadIdx.x;
    const size_t pb = (size_t)rp * HDIM;
    const size_t r0 = (size_t)(rp * 2) * HDIM;
    const size_t r1 = r0 + HDIM;

    {   // float4 gather of bufP (2 consecutive float2 per load)
        const float4* p4 = (const float4*)(g_bufP + pb + n2base);
#pragma unroll
        for (int i = tid; i < 2048; i += 512) {
            int jq = i & 3, k1 = i >> 2;
            float4 v = p4[(k1 << 7) + jq];
            smem[(2 * jq) * CSS + k1]     = make_float2(v.x, v.y);
            smem[(2 * jq + 1) * CSS + k1] = make_float2(v.z, v.w);
        }
    }
    __syncthreads();
    fft512_ip<true>(S, w1, bb, col);        // result natural in S
    __syncthreads();
    if (read_mode == 2) {
        float4* o40 = (float4*)(outf + r0 + n2base);
        float4* o41 = (float4*)(outf + r1 + n2base);
#pragma unroll
        for (int i = tid; i < 1024; i += 512) {
            int n1 = i >> 1, h = i & 1;
            int jq = h * 4;
            float2 v0 = smem[(jq + 0) * CSS + n1];
            float2 v1 = smem[(jq + 1) * CSS + n1];
            float2 v2 = smem[(jq + 2) * CSS + n1];
            float2 v3 = smem[(jq + 3) * CSS + n1];
            o40[n1 * 64 + h] = make_float4(v0.x, v1.x, v2.x, v3.x);
            o41[n1 * 64 + h] = make_float4(v0.y, v1.y, v2.y, v3.y);
        }
    } else if (read_mode == 1) {
        for (int i = tid; i < 4096; i += 512) {
            int n1 = i >> 3, j = i & 7;
            float2 v = smem[j * CSS + n1];
            size_t off = (size_t)(n1 << 8) + n2base + j;
            outc[r0 + off] = make_float2(v.x, 0.f);
            outc[r1 + off] = make_float2(v.y, 0.f);
        }
    }
}

// ---------------- launcher ----------------

extern "C" void kernel_launch(void* const* d_in, const int* in_sizes, int n_in,
                              void* d_out, int out_size) {
    const float* big[2] = {nullptr, nullptr};
    const float* ctrl = nullptr;
    int nb = 0;
    for (int i = 0; i < n_in; ++i) {
        if (in_sizes[i] == HB * 3) ctrl = (const float*)d_in[i];
        else if (in_sizes[i] == HB * HDIM && nb < 2) big[nb++] = (const float*)d_in[i];
    }
    if (nb != 2 || !ctrl) return;
    const float* z  = big[0];
    const float* tr = big[1];

    // SAFETY: every output store lies within out_size*4 bytes (minimal element size).
    const long long BD = (long long)HB * HDIM;
    long long os = out_size;
    int read_mode = 0, nt_mode = 0, tail_on = 0;
    long long tail_pos = 0;
    if (os >= 4 * BD) {              // complex-interleaved layout
        read_mode = 1; nt_mode = 2;
        tail_pos = 4 * BD; tail_on = (os >= 4 * BD + 65);
    } else if (os >= 2 * BD) {       // float32 real-part layout (os = 2BD+65)
        read_mode = 2; nt_mode = 1;
        tail_pos = 2 * BD; tail_on = (os >= 2 * BD + 65);
    } else if (os >= BD) {
        read_mode = 2;
    }

    float*  outf = (float*)d_out;
    float2* outc = (float2*)d_out;

    const int S1 = (8 * CSS) * (int)sizeof(float2);      // 41.1 KB
    const int SM = (8 * MWS) * (int)sizeof(float2);      // 51.2 KB
    cudaFuncSetAttribute(k_fwd1, cudaFuncAttributeMaxDynamicSharedMemorySize, S1);
    cudaFuncSetAttribute(k_inv2, cudaFuncAttributeMaxDynamicSharedMemorySize, S1);
    cudaFuncSetAttribute(k_mid,  cudaFuncAttributeMaxDynamicSharedMemorySize, SM);

    k_pre<<<1024, 256>>>(ctrl, (const float4*)z, (HB * HDIM) / 4, outf, tail_pos, tail_on);
    k_fwd1<<<dim3(HN2 / 8, HB), 512, S1>>>(z, tr, outf, outc, nt_mode);
    k_mid<<<dim3(HN1 / 8, HB / 2), 256, SM>>>();
    k_inv2<<<dim3(HN2 / 8, HB / 2), 512, S1>>>(outf, outc, read_mode);
}